// round 16
// baseline (speedup 1.0000x reference)
#include <cuda_runtime.h>
#include <cuda_bf16.h>
#include <cstdint>

#define N_NODES 50000
#define N_EDGES 800000
#define D       128
#define N_GR    64
#define NB_SCAN 196   // ceil(50000/256)
#define SPLIT   25024 // 64-aligned agg1/gemm2 pipeline split (391 * 64)

// -------- device scratch (no allocations allowed) --------
__device__ unsigned long long g_dcnt[N_NODES];   // fixed-point deg (low48) + count (high16)
__device__ float    g_dinv[N_NODES];
__device__ int      g_cnt [N_NODES];
__device__ int      g_cur [N_NODES];
__device__ int      g_off [N_NODES + 1];
__device__ int      g_bsum[256];
__device__ uint2    g_edge[N_EDGES];        // {src, norm-bits} per CSR slot
__device__ uint32_t g_bufA[N_NODES * 64];   // gemm1 output, bf16x2 (agg1 gathers)
__device__ uint32_t g_bufB[N_NODES * 64];   // h1 / h2, bf16x2
__device__ uint32_t g_bufC[N_NODES * 64];   // gemm2 output, bf16x2 (agg2 gathers)
__device__ float    g_pool[N_GR * D];
__device__ float    g_wr1[128 * 128];       // tf32-rounded W1 ([k][n])
__device__ float    g_wr2[128 * 128];       // tf32-rounded W2 ([k][n])

#define FIXSCALE 268435456.0f               // 2^28

// ---------------- helpers ----------------
__device__ __forceinline__ float tf32r(float x) {
    uint32_t u;
    asm("cvt.rna.tf32.f32 %0, %1;" : "=r"(u) : "f"(x));
    return __uint_as_float(u);
}

__device__ __forceinline__ uint32_t packbf(float x, float y) {
    __nv_bfloat162 h = __floats2bfloat162_rn(x, y);
    return *reinterpret_cast<uint32_t*>(&h);
}

__device__ __forceinline__ float2 u2f2(uint32_t u) {
    __nv_bfloat162 h = *reinterpret_cast<__nv_bfloat162*>(&u);
    return __bfloat1622float2(h);
}

__device__ __forceinline__ float4 u2f4(uint2 u) {
    float2 a = u2f2(u.x);
    float2 b = u2f2(u.y);
    return make_float4(a.x, a.y, b.x, b.y);
}

__device__ __forceinline__ void mma_tf32(float* c, const uint32_t* a, const uint32_t* b) {
    asm volatile("mma.sync.aligned.m16n8k8.row.col.f32.tf32.tf32.f32 "
                 "{%0,%1,%2,%3}, {%4,%5,%6,%7}, {%8,%9}, {%0,%1,%2,%3};"
                 : "+f"(c[0]), "+f"(c[1]), "+f"(c[2]), "+f"(c[3])
                 : "r"(a[0]), "r"(a[1]), "r"(a[2]), "r"(a[3]),
                   "r"(b[0]), "r"(b[1]));
}

// -------- init_b: tf32-round weights + zero pool (gemm1 depends on this) ----
__global__ void init_b_kernel(const float* __restrict__ W1,
                              const float* __restrict__ W2) {
    int i = blockIdx.x * blockDim.x + threadIdx.x;
    if (i < 128 * 128) { g_wr1[i] = tf32r(W1[i]); g_wr2[i] = tf32r(W2[i]); }
    if (i < N_GR * D) g_pool[i] = 0.0f;
}

// -------- init_a: zero CSR accumulators --------
__global__ void init_a_kernel() {
    int i = blockIdx.x * blockDim.x + threadIdx.x;
    if (i < N_NODES) { g_dcnt[i] = 0ULL; g_cur[i] = 0; }
}

// -------- per-edge: one 64-bit atomic = fixed-point deg sum + count --------
__global__ void edge_deg_kernel(const int* __restrict__ ei,
                                const float* __restrict__ ew) {
    int e = blockIdx.x * blockDim.x + threadIdx.x;
    if (e >= N_EDGES) return;
    int c = ei[N_EDGES + e];          // target node
    unsigned long long v = (1ULL << 48)
        | (unsigned long long)(long long)llrintf(ew[e] * FIXSCALE);
    atomicAdd(&g_dcnt[c], v);
}

// -------- scan1 fused with dinv --------
__global__ void scan1_kernel() {
    __shared__ int s[256];
    int t = threadIdx.x;
    int i = blockIdx.x * 256 + t;
    int v = 0;
    if (i < N_NODES) {
        unsigned long long p = g_dcnt[i];
        v = (int)(p >> 48);
        g_cnt[i] = v;
        float deg = 1.0f + (float)(long long)(p & 0xFFFFFFFFFFFFULL) * (1.0f / FIXSCALE);
        g_dinv[i] = rsqrtf(deg);
    }
    s[t] = v;
    __syncthreads();
    for (int d = 128; d > 0; d >>= 1) {
        if (t < d) s[t] += s[t + d];
        __syncthreads();
    }
    if (t == 0) g_bsum[blockIdx.x] = s[0];
}

__global__ void scan2_kernel() {
    __shared__ int s[256];
    int t = threadIdx.x;
    int v = (t < NB_SCAN) ? g_bsum[t] : 0;
    s[t] = v;
    __syncthreads();
    for (int d = 1; d < 256; d <<= 1) {
        int u = (t >= d) ? s[t - d] : 0;
        __syncthreads();
        s[t] += u;
        __syncthreads();
    }
    if (t < NB_SCAN) g_bsum[t] = s[t] - v;
}

__global__ void scan3_kernel() {
    __shared__ int s[256];
    int t = threadIdx.x;
    int i = blockIdx.x * 256 + t;
    int v = (i < N_NODES) ? g_cnt[i] : 0;
    s[t] = v;
    __syncthreads();
    for (int d = 1; d < 256; d <<= 1) {
        int u = (t >= d) ? s[t - d] : 0;
        __syncthreads();
        s[t] += u;
        __syncthreads();
    }
    int base = g_bsum[blockIdx.x];
    if (i < N_NODES) g_off[i] = base + s[t] - v;
    if (i == N_NODES - 1) g_off[N_NODES] = base + s[t];
}

// -------- fill CSR --------
__global__ void fill_kernel(const int* __restrict__ ei,
                            const float* __restrict__ ew) {
    int e = blockIdx.x * blockDim.x + threadIdx.x;
    if (e >= N_EDGES) return;
    int r = ei[e];
    int c = ei[N_EDGES + e];
    int pos = g_off[c] + atomicAdd(&g_cur[c], 1);
    float nrm = g_dinv[r] * ew[e] * g_dinv[c];
    g_edge[pos] = make_uint2((uint32_t)r, __float_as_uint(nrm));
}

// -------- tf32 mma.sync GEMM --------
// BF=false: bufA = X(fp32) @ W1 ; BF=true: bufC = bufB(bf16) @ W2
#define BM 64
#define XS_STRIDE 132
#define GEMM_SMEM_BYTES ((BM + 128) * XS_STRIDE * 4)

template <bool BF>
__global__ __launch_bounds__(256, 2) void gemm_mma(const float* __restrict__ Xext,
                                                   int blockBase) {
    extern __shared__ float sh[];
    float* Xs = sh;                       // [64][132]
    float* Ws = sh + BM * XS_STRIDE;      // [128][132]  (W[k][n])

    const float* Wr = BF ? g_wr2 : g_wr1;
    uint32_t* Yout = BF ? g_bufC : g_bufA;

    const int tid = threadIdx.x;
    const int rowBase = (blockBase + blockIdx.x) * BM;

#pragma unroll
    for (int i = 0; i < 8; i++) {
        int q = tid + 256 * i;            // 0..2047
        int r = q >> 5, c4 = q & 31;
        int rg = rowBase + r; if (rg >= N_NODES) rg = N_NODES - 1;
        float4 v;
        if (BF) {
            v = u2f4(reinterpret_cast<const uint2*>(g_bufB)[rg * 32 + c4]);
        } else {
            v = reinterpret_cast<const float4*>(Xext)[rg * 32 + c4];
        }
        float* d = &Xs[r * XS_STRIDE + c4 * 4];
        d[0] = tf32r(v.x); d[1] = tf32r(v.y); d[2] = tf32r(v.z); d[3] = tf32r(v.w);
    }
    const float4* W4 = reinterpret_cast<const float4*>(Wr);
#pragma unroll
    for (int i = 0; i < 16; i++) {
        int q = tid + 256 * i;            // 0..4095
        int r = q >> 5, c4 = q & 31;
        *reinterpret_cast<float4*>(&Ws[r * XS_STRIDE + c4 * 4]) = W4[q];
    }
    __syncthreads();

    const int lane = tid & 31, wid = tid >> 5;
    const int g = lane >> 2, t = lane & 3;
    const int mw = (wid >> 2) * 32;       // warp row offset (0/32)
    const int nw = (wid & 3) * 32;        // warp col offset (0/32/64/96)

    float c[2][4][4];
#pragma unroll
    for (int mt = 0; mt < 2; mt++)
#pragma unroll
        for (int nt = 0; nt < 4; nt++)
#pragma unroll
            for (int j = 0; j < 4; j++) c[mt][nt][j] = 0.f;

#pragma unroll 4
    for (int k0 = 0; k0 < 128; k0 += 8) {
        uint32_t a[2][4], b[4][2];
#pragma unroll
        for (int mt = 0; mt < 2; mt++) {
            const float* base = &Xs[(mw + mt * 16 + g) * XS_STRIDE + k0 + t];
            a[mt][0] = __float_as_uint(base[0]);
            a[mt][1] = __float_as_uint(base[8 * XS_STRIDE]);
            a[mt][2] = __float_as_uint(base[4]);
            a[mt][3] = __float_as_uint(base[8 * XS_STRIDE + 4]);
        }
#pragma unroll
        for (int nt = 0; nt < 4; nt++) {
            const float* bb = &Ws[(k0 + t) * XS_STRIDE + nw + nt * 8 + g];
            b[nt][0] = __float_as_uint(bb[0]);
            b[nt][1] = __float_as_uint(bb[4 * XS_STRIDE]);
        }
#pragma unroll
        for (int mt = 0; mt < 2; mt++)
#pragma unroll
            for (int nt = 0; nt < 4; nt++)
                mma_tf32(c[mt][nt], a[mt], b[nt]);
    }

#pragma unroll
    for (int mt = 0; mt < 2; mt++) {
        int row = rowBase + mw + mt * 16 + g;
#pragma unroll
        for (int nt = 0; nt < 4; nt++) {
            int ci = ((nw + nt * 8) >> 1) + t;      // bf16x2 column index
            if (row < N_NODES)
                Yout[row * 64 + ci] = packbf(c[mt][nt][0], c[mt][nt][1]);
            if (row + 8 < N_NODES)
                Yout[(row + 8) * 64 + ci] = packbf(c[mt][nt][2], c[mt][nt][3]);
        }
    }
}

#define AGG_FMA(W_, V_)                                             \
    acc.x = fmaf((W_), (V_).x, acc.x); acc.y = fmaf((W_), (V_).y, acc.y); \
    acc.z = fmaf((W_), (V_).z, acc.z); acc.w = fmaf((W_), (V_).w, acc.w);

// -------- aggregation: warp per node (round-9 proven inner loop) --------
// SECOND=false: gather bufA (layer 1); SECOND=true: gather bufC (layer 2).
template <bool SECOND>
__global__ __launch_bounds__(256) void agg_kernel(const float* __restrict__ bias,
                                                  int nodeBase) {
    const int node = nodeBase + blockIdx.x * 8 + (threadIdx.x >> 5);
    const int lane = threadIdx.x & 31;
    const uint2* in2 = reinterpret_cast<const uint2*>(SECOND ? g_bufC : g_bufA);

    float di = g_dinv[node];
    float s2 = di * di;
    float4 av = u2f4(in2[node * 32 + lane]);
    float4 acc = make_float4(s2 * av.x, s2 * av.y, s2 * av.z, s2 * av.w);

    int e  = g_off[node];
    int e1 = g_off[node + 1];
    for (; e + 3 < e1; e += 4) {
        uint2 m0 = g_edge[e],   m1 = g_edge[e+1];
        uint2 m2 = g_edge[e+2], m3 = g_edge[e+3];
        uint2 r0 = in2[m0.x * 32 + lane];
        uint2 r1 = in2[m1.x * 32 + lane];
        uint2 r2 = in2[m2.x * 32 + lane];
        uint2 r3 = in2[m3.x * 32 + lane];
        float4 v0 = u2f4(r0), v1 = u2f4(r1), v2 = u2f4(r2), v3 = u2f4(r3);
        AGG_FMA(__uint_as_float(m0.y), v0);
        AGG_FMA(__uint_as_float(m1.y), v1);
        AGG_FMA(__uint_as_float(m2.y), v2);
        AGG_FMA(__uint_as_float(m3.y), v3);
    }
    for (; e < e1; e++) {
        uint2 m = g_edge[e];
        float4 v = u2f4(in2[m.x * 32 + lane]);
        AGG_FMA(__uint_as_float(m.y), v);
    }

    float4 b = reinterpret_cast<const float4*>(bias)[lane];
    acc.x = fmaxf(acc.x + b.x, 0.f);
    acc.y = fmaxf(acc.y + b.y, 0.f);
    acc.z = fmaxf(acc.z + b.z, 0.f);
    acc.w = fmaxf(acc.w + b.w, 0.f);

    reinterpret_cast<uint2*>(g_bufB)[node * 32 + lane] =
        make_uint2(packbf(acc.x, acc.y), packbf(acc.z, acc.w));
}

// -------- pool: per-graph sums of h2 (bufB) via sorted-batch ranges --------
__global__ void pool_kernel(const int* __restrict__ batch) {
    const int g = blockIdx.x, chunk = blockIdx.y;
    const int t = threadIdx.x;

    int lo = 0, hi = N_NODES;
    while (lo < hi) { int m = (lo + hi) >> 1; if (batch[m] < g) lo = m + 1; else hi = m; }
    int s = lo;
    hi = N_NODES;
    while (lo < hi) { int m = (lo + hi) >> 1; if (batch[m] < g + 1) lo = m + 1; else hi = m; }
    int eidx = lo;

    int per = ((eidx - s) + 7) >> 3;
    int n0 = s + chunk * per;
    int n1 = n0 + per; if (n1 > eidx) n1 = eidx;

    float sum = 0.0f;
    const int cw = t >> 1, half = t & 1;
    for (int n = n0; n < n1; n++) {
        float2 p = u2f2(g_bufB[n * 64 + cw]);
        sum += half ? p.y : p.x;
    }
    atomicAdd(&g_pool[g * D + t], sum);
}

// -------- head: out[g] = (pool[g]/count) . Wh + bh --------
__global__ void final_kernel(const float* __restrict__ Wh,
                             const float* __restrict__ bh,
                             const int* __restrict__ batch,
                             float* __restrict__ out) {
    __shared__ float red[128];
    const int g = blockIdx.x;
    const int t = threadIdx.x;

    int lo = 0, hi = N_NODES;
    while (lo < hi) { int m = (lo + hi) >> 1; if (batch[m] < g) lo = m + 1; else hi = m; }
    int start = lo;
    hi = N_NODES;
    while (lo < hi) { int m = (lo + hi) >> 1; if (batch[m] < g + 1) lo = m + 1; else hi = m; }
    float c = fmaxf((float)(lo - start), 1.0f);

    float v = (g_pool[g * D + t] / c) * Wh[t];
    red[t] = v;
    __syncthreads();
    for (int s = 64; s > 0; s >>= 1) {
        if (t < s) red[t] += red[t + s];
        __syncthreads();
    }
    if (t == 0) out[g] = red[0] + bh[0];
}

extern "C" void kernel_launch(void* const* d_in, const int* in_sizes, int n_in,
                              void* d_out, int out_size) {
    const float* x     = (const float*)d_in[0];
    const float* ew    = (const float*)d_in[1];
    const float* W1    = (const float*)d_in[2];
    const float* b1    = (const float*)d_in[3];
    const float* W2    = (const float*)d_in[4];
    const float* b2    = (const float*)d_in[5];
    const float* Wh    = (const float*)d_in[6];
    const float* bh    = (const float*)d_in[7];
    const int*   ei    = (const int*)d_in[8];
    const int*   batch = (const int*)d_in[9];
    float*       out   = (float*)d_out;

    const int NB_N = (N_NODES + 255) / 256;   // 196
    const int NB_E = (N_EDGES + 255) / 256;   // 3125
    const int NB_G  = (N_NODES + BM - 1) / BM;  // 782
    const int NB_LO = SPLIT / BM;               // 391 (rows 0..25024)
    const int NB_HI = NB_G - NB_LO;             // 391 (rows 25024..50048)

    static bool ready = false;
    static cudaStream_t s1;
    static cudaEvent_t evA, evB, evC, evD;
    if (!ready) {
        cudaFuncSetAttribute(gemm_mma<false>, cudaFuncAttributeMaxDynamicSharedMemorySize,
                             GEMM_SMEM_BYTES);
        cudaFuncSetAttribute(gemm_mma<true>, cudaFuncAttributeMaxDynamicSharedMemorySize,
                             GEMM_SMEM_BYTES);
        cudaStreamCreateWithFlags(&s1, cudaStreamNonBlocking);
        cudaEventCreateWithFlags(&evA, cudaEventDisableTiming);
        cudaEventCreateWithFlags(&evB, cudaEventDisableTiming);
        cudaEventCreateWithFlags(&evC, cudaEventDisableTiming);
        cudaEventCreateWithFlags(&evD, cudaEventDisableTiming);
        ready = true;
    }

    // front section: CSR build (s0) overlapped with layer-1 GEMM (s1)
    init_b_kernel<<<64, 256>>>(W1, W2);
    cudaEventRecord(evA, 0);
    init_a_kernel<<<NB_N, 256>>>();

    cudaStreamWaitEvent(s1, evA, 0);
    gemm_mma<false><<<NB_G, 256, GEMM_SMEM_BYTES, s1>>>(x, 0);   // bufA = X @ W1
    cudaEventRecord(evB, s1);

    edge_deg_kernel<<<NB_E, 256>>>(ei, ew);
    scan1_kernel<<<NB_SCAN, 256>>>();
    scan2_kernel<<<1, 256>>>();
    scan3_kernel<<<NB_SCAN, 256>>>();
    fill_kernel<<<NB_E, 256>>>(ei, ew);

    // pipelined agg1 / gemm2 — race-free: gemm2 writes bufC, agg1 reads bufA.
    //   s0: agg1_lo | agg1_hi  gemm2_hi | agg2 ...
    //   s1:         | gemm2_lo          |
    cudaStreamWaitEvent(0, evB, 0);
    agg_kernel<false><<<SPLIT / 8, 256>>>(b1, 0);             // bufB[0,SPLIT)
    cudaEventRecord(evC, 0);

    cudaStreamWaitEvent(s1, evC, 0);
    gemm_mma<true><<<NB_LO, 256, GEMM_SMEM_BYTES, s1>>>(nullptr, 0);     // bufC lo
    cudaEventRecord(evD, s1);

    agg_kernel<false><<<(N_NODES - SPLIT) / 8, 256>>>(b1, SPLIT);        // bufB hi
    gemm_mma<true><<<NB_HI, 256, GEMM_SMEM_BYTES>>>(nullptr, NB_LO);     // bufC hi

    cudaStreamWaitEvent(0, evD, 0);
    agg_kernel<true><<<N_NODES / 8, 256>>>(b2, 0);            // h2 -> bufB (from bufC)

    pool_kernel<<<dim3(N_GR, 8), 128>>>(batch);
    final_kernel<<<N_GR, 128>>>(Wh, bh, batch, out);
}

// round 17
// speedup vs baseline: 1.0469x; 1.0469x over previous
#include <cuda_runtime.h>
#include <cuda_bf16.h>
#include <cstdint>

#define N_NODES 50000
#define N_EDGES 800000
#define D       128
#define N_GR    64
#define NB_SCAN 196   // ceil(50000/256)

// -------- device scratch (no allocations allowed) --------
__device__ unsigned long long g_dcnt[N_NODES];   // fixed-point deg (low48) + count (high16)
__device__ float    g_dinv[N_NODES];
__device__ int      g_cnt [N_NODES];
__device__ int      g_cur [N_NODES];
__device__ int      g_off [N_NODES];
__device__ int      g_base;                 // global scan base counter
__device__ uint2    g_edge[N_EDGES];        // {src, norm-bits} per CSR slot
__device__ uint32_t g_bufA[N_NODES * 64];   // gemm1 output, bf16x2 (agg1 gathers)
__device__ uint32_t g_bufB[N_NODES * 64];   // h1 / h2, bf16x2
__device__ uint32_t g_bufC[N_NODES * 64];   // gemm2 output, bf16x2 (agg2 gathers)
__device__ float    g_pool[N_GR * D];
__device__ float    g_wr1[128 * 128];       // tf32-rounded W1 ([k][n])
__device__ float    g_wr2[128 * 128];       // tf32-rounded W2 ([k][n])

#define FIXSCALE 268435456.0f               // 2^28

// ---------------- helpers ----------------
__device__ __forceinline__ float tf32r(float x) {
    uint32_t u;
    asm("cvt.rna.tf32.f32 %0, %1;" : "=r"(u) : "f"(x));
    return __uint_as_float(u);
}

__device__ __forceinline__ uint32_t packbf(float x, float y) {
    __nv_bfloat162 h = __floats2bfloat162_rn(x, y);
    return *reinterpret_cast<uint32_t*>(&h);
}

__device__ __forceinline__ float2 u2f2(uint32_t u) {
    __nv_bfloat162 h = *reinterpret_cast<__nv_bfloat162*>(&u);
    return __bfloat1622float2(h);
}

__device__ __forceinline__ float4 u2f4(uint2 u) {
    float2 a = u2f2(u.x);
    float2 b = u2f2(u.y);
    return make_float4(a.x, a.y, b.x, b.y);
}

__device__ __forceinline__ void mma_tf32(float* c, const uint32_t* a, const uint32_t* b) {
    asm volatile("mma.sync.aligned.m16n8k8.row.col.f32.tf32.tf32.f32 "
                 "{%0,%1,%2,%3}, {%4,%5,%6,%7}, {%8,%9}, {%0,%1,%2,%3};"
                 : "+f"(c[0]), "+f"(c[1]), "+f"(c[2]), "+f"(c[3])
                 : "r"(a[0]), "r"(a[1]), "r"(a[2]), "r"(a[3]),
                   "r"(b[0]), "r"(b[1]));
}

// -------- init_b: tf32-round weights + zero pool + scan base --------
__global__ void init_b_kernel(const float* __restrict__ W1,
                              const float* __restrict__ W2) {
    int i = blockIdx.x * blockDim.x + threadIdx.x;
    if (i < 128 * 128) { g_wr1[i] = tf32r(W1[i]); g_wr2[i] = tf32r(W2[i]); }
    if (i < N_GR * D) g_pool[i] = 0.0f;
    if (i == 0) g_base = 0;
}

// -------- init_a: zero CSR accumulators --------
__global__ void init_a_kernel() {
    int i = blockIdx.x * blockDim.x + threadIdx.x;
    if (i < N_NODES) { g_dcnt[i] = 0ULL; g_cur[i] = 0; }
}

// -------- per-edge: one 64-bit atomic = fixed-point deg sum + count --------
__global__ void edge_deg_kernel(const int* __restrict__ ei,
                                const float* __restrict__ ew) {
    int e = blockIdx.x * blockDim.x + threadIdx.x;
    if (e >= N_EDGES) return;
    int c = ei[N_EDGES + e];          // target node
    unsigned long long v = (1ULL << 48)
        | (unsigned long long)(long long)llrintf(ew[e] * FIXSCALE);
    atomicAdd(&g_dcnt[c], v);
}

// -------- single-pass scan: dinv + counts + atomic block base --------
// Block bases come from an atomic counter, so g_off is not globally monotone;
// each node still owns a unique contiguous CSR range [off, off+cnt).
__global__ void scan_kernel() {
    __shared__ int s[256];
    __shared__ int sbase;
    int t = threadIdx.x;
    int i = blockIdx.x * 256 + t;
    int v = 0;
    if (i < N_NODES) {
        unsigned long long p = g_dcnt[i];
        v = (int)(p >> 48);
        g_cnt[i] = v;
        float deg = 1.0f + (float)(long long)(p & 0xFFFFFFFFFFFFULL) * (1.0f / FIXSCALE);
        g_dinv[i] = rsqrtf(deg);
    }
    s[t] = v;
    __syncthreads();
    for (int d = 1; d < 256; d <<= 1) {          // inclusive scan
        int u = (t >= d) ? s[t - d] : 0;
        __syncthreads();
        s[t] += u;
        __syncthreads();
    }
    if (t == 255) sbase = atomicAdd(&g_base, s[255]);
    __syncthreads();
    if (i < N_NODES) g_off[i] = sbase + s[t] - v;  // exclusive within block
}

// -------- fill CSR --------
__global__ void fill_kernel(const int* __restrict__ ei,
                            const float* __restrict__ ew) {
    int e = blockIdx.x * blockDim.x + threadIdx.x;
    if (e >= N_EDGES) return;
    int r = ei[e];
    int c = ei[N_EDGES + e];
    int pos = g_off[c] + atomicAdd(&g_cur[c], 1);
    float nrm = g_dinv[r] * ew[e] * g_dinv[c];
    g_edge[pos] = make_uint2((uint32_t)r, __float_as_uint(nrm));
}

// -------- tf32 mma.sync GEMM --------
// BF=false: bufA = X(fp32) @ W1 ; BF=true: bufC = bufB(bf16) @ W2
#define BM 64
#define XS_STRIDE 132
#define GEMM_SMEM_BYTES ((BM + 128) * XS_STRIDE * 4)

template <bool BF>
__global__ __launch_bounds__(256, 2) void gemm_mma(const float* __restrict__ Xext) {
    extern __shared__ float sh[];
    float* Xs = sh;                       // [64][132]
    float* Ws = sh + BM * XS_STRIDE;      // [128][132]  (W[k][n])

    const float* Wr = BF ? g_wr2 : g_wr1;
    uint32_t* Yout = BF ? g_bufC : g_bufA;

    const int tid = threadIdx.x;
    const int rowBase = blockIdx.x * BM;

#pragma unroll
    for (int i = 0; i < 8; i++) {
        int q = tid + 256 * i;            // 0..2047
        int r = q >> 5, c4 = q & 31;
        int rg = rowBase + r; if (rg >= N_NODES) rg = N_NODES - 1;
        float4 v;
        if (BF) {
            v = u2f4(reinterpret_cast<const uint2*>(g_bufB)[rg * 32 + c4]);
        } else {
            v = reinterpret_cast<const float4*>(Xext)[rg * 32 + c4];
        }
        float* d = &Xs[r * XS_STRIDE + c4 * 4];
        d[0] = tf32r(v.x); d[1] = tf32r(v.y); d[2] = tf32r(v.z); d[3] = tf32r(v.w);
    }
    const float4* W4 = reinterpret_cast<const float4*>(Wr);
#pragma unroll
    for (int i = 0; i < 16; i++) {
        int q = tid + 256 * i;            // 0..4095
        int r = q >> 5, c4 = q & 31;
        *reinterpret_cast<float4*>(&Ws[r * XS_STRIDE + c4 * 4]) = W4[q];
    }
    __syncthreads();

    const int lane = tid & 31, wid = tid >> 5;
    const int g = lane >> 2, t = lane & 3;
    const int mw = (wid >> 2) * 32;       // warp row offset (0/32)
    const int nw = (wid & 3) * 32;        // warp col offset (0/32/64/96)

    float c[2][4][4];
#pragma unroll
    for (int mt = 0; mt < 2; mt++)
#pragma unroll
        for (int nt = 0; nt < 4; nt++)
#pragma unroll
            for (int j = 0; j < 4; j++) c[mt][nt][j] = 0.f;

#pragma unroll 4
    for (int k0 = 0; k0 < 128; k0 += 8) {
        uint32_t a[2][4], b[4][2];
#pragma unroll
        for (int mt = 0; mt < 2; mt++) {
            const float* base = &Xs[(mw + mt * 16 + g) * XS_STRIDE + k0 + t];
            a[mt][0] = __float_as_uint(base[0]);
            a[mt][1] = __float_as_uint(base[8 * XS_STRIDE]);
            a[mt][2] = __float_as_uint(base[4]);
            a[mt][3] = __float_as_uint(base[8 * XS_STRIDE + 4]);
        }
#pragma unroll
        for (int nt = 0; nt < 4; nt++) {
            const float* bb = &Ws[(k0 + t) * XS_STRIDE + nw + nt * 8 + g];
            b[nt][0] = __float_as_uint(bb[0]);
            b[nt][1] = __float_as_uint(bb[4 * XS_STRIDE]);
        }
#pragma unroll
        for (int mt = 0; mt < 2; mt++)
#pragma unroll
            for (int nt = 0; nt < 4; nt++)
                mma_tf32(c[mt][nt], a[mt], b[nt]);
    }

#pragma unroll
    for (int mt = 0; mt < 2; mt++) {
        int row = rowBase + mw + mt * 16 + g;
#pragma unroll
        for (int nt = 0; nt < 4; nt++) {
            int ci = ((nw + nt * 8) >> 1) + t;      // bf16x2 column index
            if (row < N_NODES)
                Yout[row * 64 + ci] = packbf(c[mt][nt][0], c[mt][nt][1]);
            if (row + 8 < N_NODES)
                Yout[(row + 8) * 64 + ci] = packbf(c[mt][nt][2], c[mt][nt][3]);
        }
    }
}

#define AGG_FMA(W_, V_)                                             \
    acc.x = fmaf((W_), (V_).x, acc.x); acc.y = fmaf((W_), (V_).y, acc.y); \
    acc.z = fmaf((W_), (V_).z, acc.z); acc.w = fmaf((W_), (V_).w, acc.w);

// -------- aggregation: warp per node (round-9 proven inner loop) --------
// e1 computed as off+cnt (g_off is per-block based, not globally monotone).
template <bool SECOND>
__global__ __launch_bounds__(256) void agg_kernel(const float* __restrict__ bias) {
    const int node = blockIdx.x * 8 + (threadIdx.x >> 5);
    const int lane = threadIdx.x & 31;
    const uint2* in2 = reinterpret_cast<const uint2*>(SECOND ? g_bufC : g_bufA);

    float di = g_dinv[node];
    float s2 = di * di;
    float4 av = u2f4(in2[node * 32 + lane]);
    float4 acc = make_float4(s2 * av.x, s2 * av.y, s2 * av.z, s2 * av.w);

    int e  = g_off[node];
    int e1 = e + g_cnt[node];
    for (; e + 3 < e1; e += 4) {
        uint2 m0 = g_edge[e],   m1 = g_edge[e+1];
        uint2 m2 = g_edge[e+2], m3 = g_edge[e+3];
        uint2 r0 = in2[m0.x * 32 + lane];
        uint2 r1 = in2[m1.x * 32 + lane];
        uint2 r2 = in2[m2.x * 32 + lane];
        uint2 r3 = in2[m3.x * 32 + lane];
        float4 v0 = u2f4(r0), v1 = u2f4(r1), v2 = u2f4(r2), v3 = u2f4(r3);
        AGG_FMA(__uint_as_float(m0.y), v0);
        AGG_FMA(__uint_as_float(m1.y), v1);
        AGG_FMA(__uint_as_float(m2.y), v2);
        AGG_FMA(__uint_as_float(m3.y), v3);
    }
    for (; e < e1; e++) {
        uint2 m = g_edge[e];
        float4 v = u2f4(in2[m.x * 32 + lane]);
        AGG_FMA(__uint_as_float(m.y), v);
    }

    float4 b = reinterpret_cast<const float4*>(bias)[lane];
    acc.x = fmaxf(acc.x + b.x, 0.f);
    acc.y = fmaxf(acc.y + b.y, 0.f);
    acc.z = fmaxf(acc.z + b.z, 0.f);
    acc.w = fmaxf(acc.w + b.w, 0.f);

    reinterpret_cast<uint2*>(g_bufB)[node * 32 + lane] =
        make_uint2(packbf(acc.x, acc.y), packbf(acc.z, acc.w));
}

// -------- pool: per-graph sums of h2 (bufB) via sorted-batch ranges --------
__global__ void pool_kernel(const int* __restrict__ batch) {
    const int g = blockIdx.x, chunk = blockIdx.y;
    const int t = threadIdx.x;

    int lo = 0, hi = N_NODES;
    while (lo < hi) { int m = (lo + hi) >> 1; if (batch[m] < g) lo = m + 1; else hi = m; }
    int s = lo;
    hi = N_NODES;
    while (lo < hi) { int m = (lo + hi) >> 1; if (batch[m] < g + 1) lo = m + 1; else hi = m; }
    int eidx = lo;

    int per = ((eidx - s) + 7) >> 3;
    int n0 = s + chunk * per;
    int n1 = n0 + per; if (n1 > eidx) n1 = eidx;

    float sum = 0.0f;
    const int cw = t >> 1, half = t & 1;
    for (int n = n0; n < n1; n++) {
        float2 p = u2f2(g_bufB[n * 64 + cw]);
        sum += half ? p.y : p.x;
    }
    atomicAdd(&g_pool[g * D + t], sum);
}

// -------- head: out[g] = (pool[g]/count) . Wh + bh --------
__global__ void final_kernel(const float* __restrict__ Wh,
                             const float* __restrict__ bh,
                             const int* __restrict__ batch,
                             float* __restrict__ out) {
    __shared__ float red[128];
    const int g = blockIdx.x;
    const int t = threadIdx.x;

    int lo = 0, hi = N_NODES;
    while (lo < hi) { int m = (lo + hi) >> 1; if (batch[m] < g) lo = m + 1; else hi = m; }
    int start = lo;
    hi = N_NODES;
    while (lo < hi) { int m = (lo + hi) >> 1; if (batch[m] < g + 1) lo = m + 1; else hi = m; }
    float c = fmaxf((float)(lo - start), 1.0f);

    float v = (g_pool[g * D + t] / c) * Wh[t];
    red[t] = v;
    __syncthreads();
    for (int s = 64; s > 0; s >>= 1) {
        if (t < s) red[t] += red[t + s];
        __syncthreads();
    }
    if (t == 0) out[g] = red[0] + bh[0];
}

extern "C" void kernel_launch(void* const* d_in, const int* in_sizes, int n_in,
                              void* d_out, int out_size) {
    const float* x     = (const float*)d_in[0];
    const float* ew    = (const float*)d_in[1];
    const float* W1    = (const float*)d_in[2];
    const float* b1    = (const float*)d_in[3];
    const float* W2    = (const float*)d_in[4];
    const float* b2    = (const float*)d_in[5];
    const float* Wh    = (const float*)d_in[6];
    const float* bh    = (const float*)d_in[7];
    const int*   ei    = (const int*)d_in[8];
    const int*   batch = (const int*)d_in[9];
    float*       out   = (float*)d_out;

    const int NB_N = (N_NODES + 255) / 256;   // 196
    const int NB_E = (N_EDGES + 255) / 256;   // 3125
    const int NB_G = (N_NODES + BM - 1) / BM; // 782

    static bool ready = false;
    static cudaStream_t s1;
    static cudaEvent_t evA, evB;
    if (!ready) {
        cudaFuncSetAttribute(gemm_mma<false>, cudaFuncAttributeMaxDynamicSharedMemorySize,
                             GEMM_SMEM_BYTES);
        cudaFuncSetAttribute(gemm_mma<true>, cudaFuncAttributeMaxDynamicSharedMemorySize,
                             GEMM_SMEM_BYTES);
        cudaStreamCreateWithFlags(&s1, cudaStreamNonBlocking);
        cudaEventCreateWithFlags(&evA, cudaEventDisableTiming);
        cudaEventCreateWithFlags(&evB, cudaEventDisableTiming);
        ready = true;
    }

    // front section: CSR build (s0) overlapped with layer-1 GEMM (s1)
    init_b_kernel<<<64, 256>>>(W1, W2);
    cudaEventRecord(evA, 0);
    init_a_kernel<<<NB_N, 256>>>();

    cudaStreamWaitEvent(s1, evA, 0);
    gemm_mma<false><<<NB_G, 256, GEMM_SMEM_BYTES, s1>>>(x);   // bufA = X @ W1
    cudaEventRecord(evB, s1);

    edge_deg_kernel<<<NB_E, 256>>>(ei, ew);
    scan_kernel<<<NB_SCAN, 256>>>();
    fill_kernel<<<NB_E, 256>>>(ei, ew);

    // join, then sequential layer work (pipeline split measured neutral)
    cudaStreamWaitEvent(0, evB, 0);
    agg_kernel<false><<<N_NODES / 8, 256>>>(b1);       // bufB = agg(bufA)
    gemm_mma<true><<<NB_G, 256, GEMM_SMEM_BYTES>>>(nullptr);  // bufC = bufB @ W2
    agg_kernel<true><<<N_NODES / 8, 256>>>(b2);        // bufB = agg(bufC)

    pool_kernel<<<dim3(N_GR, 8), 128>>>(batch);
    final_kernel<<<N_GR, 128>>>(Wh, bh, batch, out);
}